// round 7
// baseline (speedup 1.0000x reference)
#include <cuda_runtime.h>

#define H_IMG 512
#define W_IMG 512
#define NPLANES 96            // 32 * 3
#define TW 32
#define TH 32
#define IW 42                 // TW + 10
#define IH 42                 // TH + 10
#define SS 44                 // staged stride: 16B-aligned rows, conflict-free for LDS.128
#define MS 36                 // intermediate stride: 16B-aligned, conflict-free
#define NT 256
#define NBX 16                // 512/32
#define NBY 16                // 512/32
#define NBLK (NBX * NBY * NPLANES)   // 24576
#define C1F 6.5025f
#define C2F 58.5225f
#define NPIX 25165824.0       // 32*3*512*512

__device__ float g_partials[NBLK];
__device__ unsigned int g_count = 0;

#define W11_INIT {0.00102838f, 0.00759871f, 0.03600077f, 0.10936070f, \
                  0.21300560f, 0.26601180f, 0.21300560f, 0.10936070f, \
                  0.03600077f, 0.00759871f, 0.00102838f}

__global__ void __launch_bounds__(NT, 4) ssim_main(const float* __restrict__ gen,
                                                   const float* __restrict__ ref,
                                                   float* __restrict__ out) {
    __shared__ float sg[IH * SS];      // staged gen (scaled)
    __shared__ float sr[IH * SS];      // staged ref (scaled)
    __shared__ float m1[IH * MS];      // conv_h(g)
    __shared__ float m2[IH * MS];      // conv_h(r)
    __shared__ float mss[IH * MS];     // conv_h(g^2 + r^2)
    __shared__ float mgr[IH * MS];     // conv_h(g*r)
    __shared__ float wsum[8];
    __shared__ double dsum[8];
    __shared__ bool is_last;

    const float W11[11] = W11_INIT;    // compile-time consts -> FFMA-imm

    const int tid = threadIdx.x;
    const int lane = tid & 31;
    const int wrp = tid >> 5;
    const int x0 = blockIdx.x * TW;
    const int y0 = blockIdx.y * TH;
    const size_t pb = (size_t)blockIdx.z * (size_t)(H_IMG * W_IMG);
    const float* gp = gen + pb;
    const float* rp = ref + pb;

    // ---- Stage 0: coalesced load of tile+halo, scale, zero-pad ----
    const bool interior = (x0 >= 5) & (x0 + IW - 5 <= W_IMG) &
                          (y0 >= 5) & (y0 + IH - 5 <= H_IMG);
    if (interior) {
        const float* gb = gp + (long)(y0 - 5) * W_IMG + (x0 - 5);
        const float* rb = rp + (long)(y0 - 5) * W_IMG + (x0 - 5);
#pragma unroll 2
        for (int i = tid; i < IH * IW; i += NT) {
            int r = i / IW;
            int c = i - r * IW;
            int idx = r * W_IMG + c;
            sg[r * SS + c] = fmaf(gb[idx], 0.5f, 0.5f);
            sr[r * SS + c] = fmaf(rb[idx], 0.5f, 0.5f);
        }
    } else {
#pragma unroll 2
        for (int i = tid; i < IH * IW; i += NT) {
            int r = i / IW;
            int c = i - r * IW;
            int gy = y0 + r - 5;
            int gx = x0 + c - 5;
            float gv = 0.f, rv = 0.f;
            if ((unsigned)gy < (unsigned)H_IMG && (unsigned)gx < (unsigned)W_IMG) {
                int idx = gy * W_IMG + gx;
                gv = fmaf(gp[idx], 0.5f, 0.5f);
                rv = fmaf(rp[idx], 0.5f, 0.5f);
            }
            sg[r * SS + c] = gv;
            sr[r * SS + c] = rv;
        }
    }
    __syncthreads();

    // ---- Stage 1: horizontal conv, 4 fields, 8 output cols per item ----
    // items: 42 rows x 4 col-chunks of 8 = 168  (single balanced pass)
    if (tid < IH * 4) {
        const int r = tid >> 2;
        const int c0 = (tid & 3) << 3;
        const float* sgr = sg + r * SS + c0;
        const float* srr = sr + r * SS + c0;
        const int o = r * MS + c0;

        // vectorized window loads: 18 floats = 4x float4 + 1x float2
        float a[18], b[18];
        {
            const float4* p4 = reinterpret_cast<const float4*>(sgr);
            const float4* q4 = reinterpret_cast<const float4*>(srr);
#pragma unroll
            for (int t = 0; t < 4; t++) {
                float4 va = p4[t], vb = q4[t];
                a[4*t+0] = va.x; a[4*t+1] = va.y; a[4*t+2] = va.z; a[4*t+3] = va.w;
                b[4*t+0] = vb.x; b[4*t+1] = vb.y; b[4*t+2] = vb.z; b[4*t+3] = vb.w;
            }
            float2 ta = *reinterpret_cast<const float2*>(sgr + 16);
            float2 tb = *reinterpret_cast<const float2*>(srr + 16);
            a[16] = ta.x; a[17] = ta.y;
            b[16] = tb.x; b[17] = tb.y;
        }

        // first moments
        {
            float s1[8], s2[8];
#pragma unroll
            for (int j = 0; j < 8; j++) { s1[j] = 0.f; s2[j] = 0.f; }
#pragma unroll
            for (int k = 0; k < 11; k++) {
#pragma unroll
                for (int j = 0; j < 8; j++) {
                    s1[j] = fmaf(W11[k], a[k + j], s1[j]);
                    s2[j] = fmaf(W11[k], b[k + j], s2[j]);
                }
            }
            reinterpret_cast<float4*>(m1 + o)[0] = make_float4(s1[0], s1[1], s1[2], s1[3]);
            reinterpret_cast<float4*>(m1 + o)[1] = make_float4(s1[4], s1[5], s1[6], s1[7]);
            reinterpret_cast<float4*>(m2 + o)[0] = make_float4(s2[0], s2[1], s2[2], s2[3]);
            reinterpret_cast<float4*>(m2 + o)[1] = make_float4(s2[4], s2[5], s2[6], s2[7]);
        }

        // in-place transform: a <- g^2 + r^2,  b <- g*r
#pragma unroll
        for (int t = 0; t < 18; t++) {
            float pa = a[t];
            float pbv = b[t];
            a[t] = fmaf(pa, pa, pbv * pbv);
            b[t] = pa * pbv;
        }

        // second moments
        {
            float s3[8], s4[8];
#pragma unroll
            for (int j = 0; j < 8; j++) { s3[j] = 0.f; s4[j] = 0.f; }
#pragma unroll
            for (int k = 0; k < 11; k++) {
#pragma unroll
                for (int j = 0; j < 8; j++) {
                    s3[j] = fmaf(W11[k], a[k + j], s3[j]);
                    s4[j] = fmaf(W11[k], b[k + j], s4[j]);
                }
            }
            reinterpret_cast<float4*>(mss + o)[0] = make_float4(s3[0], s3[1], s3[2], s3[3]);
            reinterpret_cast<float4*>(mss + o)[1] = make_float4(s3[4], s3[5], s3[6], s3[7]);
            reinterpret_cast<float4*>(mgr + o)[0] = make_float4(s4[0], s4[1], s4[2], s4[3]);
            reinterpret_cast<float4*>(mgr + o)[1] = make_float4(s4[4], s4[5], s4[6], s4[7]);
        }
    }
    __syncthreads();

    // ---- Stage 2: vertical conv (4 rows/thread), streaming SSIM combine ----
    float lsum = 0.f;
    {
        const int c = lane;
        const int r0 = wrp << 2;       // 8 warps * 4 rows = 32

#define VCONV(MARR, OUT)                                                  \
        {                                                                 \
            float v[14];                                                  \
            _Pragma("unroll")                                             \
            for (int t = 0; t < 14; t++) v[t] = MARR[(r0 + t) * MS + c];  \
            _Pragma("unroll")                                             \
            for (int j = 0; j < 4; j++) {                                 \
                float acc = 0.f;                                          \
                _Pragma("unroll")                                         \
                for (int k = 0; k < 11; k++)                              \
                    acc = fmaf(W11[k], v[j + k], acc);                    \
                OUT[j] = acc;                                             \
            }                                                             \
        }

        float q[4], p[4];              // mu1^2+mu2^2, mu1*mu2
        {
            float o1[4], o2[4];
            VCONV(m1, o1)
            VCONV(m2, o2)
#pragma unroll
            for (int j = 0; j < 4; j++) {
                q[j] = fmaf(o1[j], o1[j], o2[j] * o2[j]);
                p[j] = o1[j] * o2[j];
            }
        }
        float dden[4];
        {
            float oss[4];
            VCONV(mss, oss)
#pragma unroll
            for (int j = 0; j < 4; j++)
                dden[j] = (q[j] + C1F) * (oss[j] - q[j] + C2F);
        }
        {
            float ogr[4];
            VCONV(mgr, ogr)
#pragma unroll
            for (int j = 0; j < 4; j++) {
                float num = fmaf(2.f, p[j], C1F) * fmaf(2.f, ogr[j] - p[j], C2F);
                lsum += __fdividef(num, dden[j]);
            }
        }
#undef VCONV
    }

    // ---- Block reduction (fp32) ----
#pragma unroll
    for (int off = 16; off > 0; off >>= 1)
        lsum += __shfl_xor_sync(0xffffffffu, lsum, off);
    if (lane == 0) wsum[wrp] = lsum;
    __syncthreads();

    if (tid == 0) {
        float s = 0.f;
#pragma unroll
        for (int i = 0; i < 8; i++) s += wsum[i];
        int bid = blockIdx.x + NBX * (blockIdx.y + NBY * blockIdx.z);
        g_partials[bid] = s;
        __threadfence();
        unsigned int t = atomicAdd(&g_count, 1u);
        is_last = (t == (unsigned)(NBLK - 1));
    }
    __syncthreads();

    // ---- Last block: deterministic final reduction ----
    if (is_last) {
        __threadfence();
        double acc = 0.0;
        for (int i = tid; i < NBLK; i += NT)
            acc += (double)g_partials[i];
#pragma unroll
        for (int off = 16; off > 0; off >>= 1)
            acc += __shfl_xor_sync(0xffffffffu, acc, off);
        if (lane == 0) dsum[wrp] = acc;
        __syncthreads();
        if (tid == 0) {
            double s = 0.0;
#pragma unroll
            for (int i = 0; i < 8; i++) s += dsum[i];
            out[0] = (float)(1.0 - s / NPIX);
            g_count = 0;   // self-reset -> graph-replay deterministic
        }
    }
}

extern "C" void kernel_launch(void* const* d_in, const int* in_sizes, int n_in,
                              void* d_out, int out_size) {
    const float* gen = (const float*)d_in[0];
    const float* ref = (const float*)d_in[1];
    float* out = (float*)d_out;

    dim3 grid(NBX, NBY, NPLANES);
    ssim_main<<<grid, NT>>>(gen, ref, out);
}

// round 8
// speedup vs baseline: 1.2073x; 1.2073x over previous
#include <cuda_runtime.h>

#define H_IMG 512
#define W_IMG 512
#define NPLANES 96            // 32 * 3
#define TW 32
#define TH 32
#define IW 42                 // TW + 10
#define IH 42                 // TH + 10
#define SS 43                 // staged-input smem row stride (odd -> conflict-free)
#define MS 33                 // intermediate smem row stride (conflict-free)
#define NT 256
#define NBX 16                // 512/32
#define NBY 16                // 512/32
#define NBLK (NBX * NBY * NPLANES)   // 24576
#define C1F 6.5025f
#define C2F 58.5225f
#define NPIX 25165824.0       // 32*3*512*512

__device__ float g_partials[NBLK];
__device__ unsigned int g_count = 0;

#define W11_INIT {0.00102838f, 0.00759871f, 0.03600077f, 0.10936070f, \
                  0.21300560f, 0.26601180f, 0.21300560f, 0.10936070f, \
                  0.03600077f, 0.00759871f, 0.00102838f}

__global__ void __launch_bounds__(NT, 5) ssim_main(const float* __restrict__ gen,
                                                   const float* __restrict__ ref,
                                                   float* __restrict__ out) {
    __shared__ float sg[IH * SS];      // staged gen (scaled)
    __shared__ float sr[IH * SS];      // staged ref (scaled)
    __shared__ float m1[IH * MS];      // conv_h(g)
    __shared__ float m2[IH * MS];      // conv_h(r)
    __shared__ float mss[IH * MS];     // conv_h(g^2 + r^2)
    __shared__ float mgr[IH * MS];     // conv_h(g*r)
    __shared__ float wsum[8];
    __shared__ double dsum[8];
    __shared__ bool is_last;

    const float W11[11] = W11_INIT;    // compile-time consts -> FFMA-imm

    const int tid = threadIdx.x;
    const int lane = tid & 31;
    const int wrp = tid >> 5;
    const int x0 = blockIdx.x * TW;
    const int y0 = blockIdx.y * TH;
    const size_t pb = (size_t)blockIdx.z * (size_t)(H_IMG * W_IMG);
    const float* gp = gen + pb;
    const float* rp = ref + pb;

    // ---- Stage 0: warp-per-row coalesced load, scale, zero-pad ----
    const bool interior = (x0 >= 5) & (x0 + IW - 5 <= W_IMG) &
                          (y0 >= 5) & (y0 + IH - 5 <= H_IMG);
    if (interior) {
        const float* gb = gp + (long)(y0 - 5) * W_IMG + (x0 - 5);
        const float* rb = rp + (long)(y0 - 5) * W_IMG + (x0 - 5);
#pragma unroll
        for (int r = wrp; r < IH; r += 8) {
            const float* grow = gb + (long)r * W_IMG;
            const float* rrow = rb + (long)r * W_IMG;
            float* sgrow = sg + r * SS;
            float* srrow = sr + r * SS;
            sgrow[lane] = fmaf(grow[lane], 0.5f, 0.5f);
            srrow[lane] = fmaf(rrow[lane], 0.5f, 0.5f);
            if (lane < IW - 32) {
                sgrow[lane + 32] = fmaf(grow[lane + 32], 0.5f, 0.5f);
                srrow[lane + 32] = fmaf(rrow[lane + 32], 0.5f, 0.5f);
            }
        }
    } else {
#pragma unroll
        for (int r = wrp; r < IH; r += 8) {
            int gy = y0 + r - 5;
            bool rowok = (unsigned)gy < (unsigned)H_IMG;
            const float* grow = gp + (long)gy * W_IMG;
            const float* rrow = rp + (long)gy * W_IMG;
            float* sgrow = sg + r * SS;
            float* srrow = sr + r * SS;
#pragma unroll
            for (int h = 0; h < 2; h++) {
                int c = lane + h * 32;
                if (c < IW) {
                    int gx = x0 + c - 5;
                    bool ok = rowok && ((unsigned)gx < (unsigned)W_IMG);
                    sgrow[c] = ok ? fmaf(grow[gx], 0.5f, 0.5f) : 0.f;
                    srrow[c] = ok ? fmaf(rrow[gx], 0.5f, 0.5f) : 0.f;
                }
            }
        }
    }
    __syncthreads();

    // ---- Stage 1: horizontal conv, 4 fields, 4 output cols per item ----
    // items: 42 rows x 8 col-chunks of 4 = 336
    for (int item = tid; item < IH * 8; item += NT) {
        int r = item >> 3;
        int c0 = (item & 7) << 2;
        const float* sgr = sg + r * SS + c0;
        const float* srr = sr + r * SS + c0;
        const int o = r * MS + c0;

        float a[14], b[14];
#pragma unroll
        for (int t = 0; t < 14; t++) { a[t] = sgr[t]; b[t] = srr[t]; }

        // first moments
        {
            float s1[4] = {0.f, 0.f, 0.f, 0.f};
            float s2[4] = {0.f, 0.f, 0.f, 0.f};
#pragma unroll
            for (int k = 0; k < 11; k++) {
#pragma unroll
                for (int j = 0; j < 4; j++) {
                    s1[j] = fmaf(W11[k], a[k + j], s1[j]);
                    s2[j] = fmaf(W11[k], b[k + j], s2[j]);
                }
            }
#pragma unroll
            for (int j = 0; j < 4; j++) { m1[o + j] = s1[j]; m2[o + j] = s2[j]; }
        }

        // in-place transform: a <- g^2 + r^2,  b <- g*r
#pragma unroll
        for (int t = 0; t < 14; t++) {
            float pa = a[t];
            float pbv = b[t];
            a[t] = fmaf(pa, pa, pbv * pbv);
            b[t] = pa * pbv;
        }

        // second moments
        {
            float s3[4] = {0.f, 0.f, 0.f, 0.f};
            float s4[4] = {0.f, 0.f, 0.f, 0.f};
#pragma unroll
            for (int k = 0; k < 11; k++) {
#pragma unroll
                for (int j = 0; j < 4; j++) {
                    s3[j] = fmaf(W11[k], a[k + j], s3[j]);
                    s4[j] = fmaf(W11[k], b[k + j], s4[j]);
                }
            }
#pragma unroll
            for (int j = 0; j < 4; j++) { mss[o + j] = s3[j]; mgr[o + j] = s4[j]; }
        }
    }
    __syncthreads();

    // ---- Stage 2: vertical conv (4 rows/thread), streaming SSIM combine ----
    float lsum = 0.f;
    {
        const int c = lane;
        const int r0 = wrp << 2;       // 8 warps * 4 rows = 32

#define VCONV(MARR, OUT)                                                  \
        {                                                                 \
            float v[14];                                                  \
            _Pragma("unroll")                                             \
            for (int t = 0; t < 14; t++) v[t] = MARR[(r0 + t) * MS + c];  \
            _Pragma("unroll")                                             \
            for (int j = 0; j < 4; j++) {                                 \
                float acc = 0.f;                                          \
                _Pragma("unroll")                                         \
                for (int k = 0; k < 11; k++)                              \
                    acc = fmaf(W11[k], v[j + k], acc);                    \
                OUT[j] = acc;                                             \
            }                                                             \
        }

        float q[4], p[4];              // mu1^2+mu2^2, mu1*mu2
        {
            float o1[4], o2[4];
            VCONV(m1, o1)
            VCONV(m2, o2)
#pragma unroll
            for (int j = 0; j < 4; j++) {
                q[j] = fmaf(o1[j], o1[j], o2[j] * o2[j]);
                p[j] = o1[j] * o2[j];
            }
        }
        float dden[4];
        {
            float oss[4];
            VCONV(mss, oss)
#pragma unroll
            for (int j = 0; j < 4; j++)
                dden[j] = (q[j] + C1F) * (oss[j] - q[j] + C2F);
        }
        {
            float ogr[4];
            VCONV(mgr, ogr)
#pragma unroll
            for (int j = 0; j < 4; j++) {
                float num = fmaf(2.f, p[j], C1F) * fmaf(2.f, ogr[j] - p[j], C2F);
                lsum += __fdividef(num, dden[j]);
            }
        }
#undef VCONV
    }

    // ---- Block reduction (fp32) ----
#pragma unroll
    for (int off = 16; off > 0; off >>= 1)
        lsum += __shfl_xor_sync(0xffffffffu, lsum, off);
    if (lane == 0) wsum[wrp] = lsum;
    __syncthreads();

    if (tid == 0) {
        float s = 0.f;
#pragma unroll
        for (int i = 0; i < 8; i++) s += wsum[i];
        int bid = blockIdx.x + NBX * (blockIdx.y + NBY * blockIdx.z);
        g_partials[bid] = s;
        __threadfence();
        unsigned int t = atomicAdd(&g_count, 1u);
        is_last = (t == (unsigned)(NBLK - 1));
    }
    __syncthreads();

    // ---- Last block: deterministic final reduction ----
    if (is_last) {
        __threadfence();
        double acc = 0.0;
        for (int i = tid; i < NBLK; i += NT)
            acc += (double)g_partials[i];
#pragma unroll
        for (int off = 16; off > 0; off >>= 1)
            acc += __shfl_xor_sync(0xffffffffu, acc, off);
        if (lane == 0) dsum[wrp] = acc;
        __syncthreads();
        if (tid == 0) {
            double s = 0.0;
#pragma unroll
            for (int i = 0; i < 8; i++) s += dsum[i];
            out[0] = (float)(1.0 - s / NPIX);
            g_count = 0;   // self-reset -> graph-replay deterministic
        }
    }
}

extern "C" void kernel_launch(void* const* d_in, const int* in_sizes, int n_in,
                              void* d_out, int out_size) {
    const float* gen = (const float*)d_in[0];
    const float* ref = (const float*)d_in[1];
    float* out = (float*)d_out;

    dim3 grid(NBX, NBY, NPLANES);
    ssim_main<<<grid, NT>>>(gen, ref, out);
}